// round 1
// baseline (speedup 1.0000x reference)
#include <cuda_runtime.h>
#include <cuda_bf16.h>
#include <mma.h>

using namespace nvcuda;

#define NROWS 8192          // 2N
#define HALF_N 4096
#define D 256               // feature dim
#define TEMP_INV 2.0f       // 1/temperature

#define MT 64               // rows per block
#define NT 128              // cols per chunk
#define THREADS 256

// Scratch (device globals — no allocation allowed)
__device__ __nv_bfloat16 g_zn[NROWS * D];   // normalized rows, bf16 (4 MB)
__device__ float g_loss[NROWS];             // per-row loss

// ---------------------------------------------------------------------------
// Kernel 1: L2-normalize each row of concat(z1, z2), store bf16.
// One block per row; 256 threads == D.
// ---------------------------------------------------------------------------
__global__ void norm_kernel(const float* __restrict__ z1,
                            const float* __restrict__ z2) {
    int row = blockIdx.x;
    const float* src = (row < HALF_N) ? (z1 + (size_t)row * D)
                                      : (z2 + (size_t)(row - HALF_N) * D);
    int t = threadIdx.x;
    float v = src[t];

    __shared__ float red[THREADS];
    red[t] = v * v;
    __syncthreads();
    #pragma unroll
    for (int s = 128; s > 0; s >>= 1) {
        if (t < s) red[t] += red[t + s];
        __syncthreads();
    }
    float norm = fmaxf(sqrtf(red[0]), 1e-8f);
    g_zn[(size_t)row * D + t] = __float2bfloat16(v / norm);
}

// ---------------------------------------------------------------------------
// Kernel 2: fused sim-GEMM + exp-rowsum + diagonal removal + positive gather.
// Grid: 128 blocks (8192 / MT). Each block owns MT=64 rows, loops all 8192
// cols in NT=128 chunks. wmma bf16 m16n16k16, accum fp32.
// Dynamic smem layout:
//   A tile   MT x D  bf16  = 32 KB
//   B tile   NT x D  bf16  = 64 KB
//   C tile   MT x NT fp32  = 32 KB
//   rowAcc / rowDiag / rowPos : MT floats each
// ---------------------------------------------------------------------------
__global__ void sim_kernel() {
    extern __shared__ char smem[];
    __nv_bfloat16* Asm = (__nv_bfloat16*)smem;                       // 32768 B
    __nv_bfloat16* Bsm = (__nv_bfloat16*)(smem + 32768);             // 65536 B
    float*         Csm = (float*)(smem + 32768 + 65536);             // 32768 B
    float*      rowAcc = (float*)(smem + 32768 + 65536 + 32768);
    float*     rowDiag = rowAcc + MT;
    float*      rowPos = rowDiag + MT;

    int tid = threadIdx.x;
    int ibase = blockIdx.x * MT;

    // Load A tile once (64 x 256 bf16 = 8192 uint32 loads across 256 threads)
    {
        const unsigned int* gA = (const unsigned int*)(g_zn + (size_t)ibase * D);
        unsigned int* As = (unsigned int*)Asm;
        #pragma unroll
        for (int k = tid; k < MT * D / 2; k += THREADS) As[k] = gA[k];
    }
    if (tid < MT) { rowAcc[tid] = 0.0f; rowDiag[tid] = 0.0f; rowPos[tid] = 0.0f; }
    __syncthreads();

    int w  = tid >> 5;            // warp id 0..7
    int wm = w & 3;               // warp row group (16 rows)
    int wn = (w >> 2) * 64;       // warp col base (0 or 64)

    // per-thread epilogue mapping: 4 threads per row, 32 cols each
    int er  = tid >> 2;
    int ecg = (tid & 3) * 32;
    int gi   = ibase + er;
    int gpos = (gi < HALF_N) ? gi + HALF_N : gi - HALF_N;

    for (int jb = 0; jb < NROWS; jb += NT) {
        // Load B tile (128 x 256 bf16)
        {
            const unsigned int* gB = (const unsigned int*)(g_zn + (size_t)jb * D);
            unsigned int* Bs = (unsigned int*)Bsm;
            #pragma unroll
            for (int k = tid; k < NT * D / 2; k += THREADS) Bs[k] = gB[k];
        }
        __syncthreads();   // B ready; also guarantees prior epilogue done before C rewrite

        // MMA: each warp computes 16 x 64 of C
        wmma::fragment<wmma::accumulator, 16, 16, 16, float> cfrag[4];
        #pragma unroll
        for (int f = 0; f < 4; f++) wmma::fill_fragment(cfrag[f], 0.0f);

        #pragma unroll
        for (int k = 0; k < D; k += 16) {
            wmma::fragment<wmma::matrix_a, 16, 16, 16, __nv_bfloat16, wmma::row_major> afrag;
            wmma::load_matrix_sync(afrag, Asm + wm * 16 * D + k, D);
            #pragma unroll
            for (int f = 0; f < 4; f++) {
                wmma::fragment<wmma::matrix_b, 16, 16, 16, __nv_bfloat16, wmma::col_major> bfrag;
                wmma::load_matrix_sync(bfrag, Bsm + (wn + f * 16) * D + k, D);
                wmma::mma_sync(cfrag[f], afrag, bfrag, cfrag[f]);
            }
        }
        #pragma unroll
        for (int f = 0; f < 4; f++)
            wmma::store_matrix_sync(Csm + wm * 16 * NT + wn + f * 16, cfrag[f],
                                    NT, wmma::mem_row_major);
        __syncthreads();

        // Epilogue: exp + row accumulate; detect diagonal / positive
        float lsum = 0.0f;
        #pragma unroll
        for (int c = 0; c < 32; c++) {
            int gj = jb + ecg + c;
            float sim = Csm[er * NT + ecg + c] * TEMP_INV;
            float e = __expf(sim);
            lsum += e;
            if (gj == gi)   rowDiag[er] = e;     // unique writer
            if (gj == gpos) rowPos[er]  = sim;   // unique writer
        }
        // reduce 4 adjacent lanes (same row)
        lsum += __shfl_down_sync(0xffffffffu, lsum, 1);
        lsum += __shfl_down_sync(0xffffffffu, lsum, 2);
        if ((tid & 3) == 0) rowAcc[er] += lsum;  // single writer per row
        __syncthreads();
    }

    if (tid < MT) {
        float S = rowAcc[tid] - rowDiag[tid];    // exact diagonal removal
        g_loss[ibase + tid] = logf(S) - rowPos[tid];
    }
}

// ---------------------------------------------------------------------------
// Kernel 3: deterministic mean reduction of per-row losses.
// ---------------------------------------------------------------------------
__global__ void reduce_kernel(float* __restrict__ out) {
    __shared__ float red[THREADS];
    int t = threadIdx.x;
    float s = 0.0f;
    for (int i = t; i < NROWS; i += THREADS) s += g_loss[i];
    red[t] = s;
    __syncthreads();
    #pragma unroll
    for (int k = 128; k > 0; k >>= 1) {
        if (t < k) red[t] += red[t + k];
        __syncthreads();
    }
    if (t == 0) out[0] = red[0] / (float)NROWS;
}

// ---------------------------------------------------------------------------
extern "C" void kernel_launch(void* const* d_in, const int* in_sizes, int n_in,
                              void* d_out, int out_size) {
    const float* z1 = (const float*)d_in[0];
    const float* z2 = (const float*)d_in[1];
    float* out = (float*)d_out;

    const int SMEM_BYTES = 32768 + 65536 + 32768 + 3 * MT * (int)sizeof(float);
    cudaFuncSetAttribute(sim_kernel,
                         cudaFuncAttributeMaxDynamicSharedMemorySize, SMEM_BYTES);

    norm_kernel<<<NROWS, THREADS>>>(z1, z2);
    sim_kernel<<<NROWS / MT, THREADS, SMEM_BYTES>>>();
    reduce_kernel<<<1, THREADS>>>(out);
}

// round 3
// speedup vs baseline: 8.3490x; 8.3490x over previous
#include <cuda_runtime.h>
#include <cuda_bf16.h>
#include <cstdint>

#define NROWS  8192
#define HALF_N 4096
#define D      256
#define MT     128            // rows per CTA
#define NT     128            // cols per tile
#define TIL    32             // 4096 / NT tiles per CTA (one col-half)
#define THREADS 256

// smem: A tile @0 (64KB), B buf0 @65536, B buf1 @131072
#define SM_A  0
#define SM_B0 65536
#define SMEM_TOTAL (3 * 65536)

__device__ __nv_bfloat16 g_zn[NROWS * D];   // normalized rows (4 MB, L2-resident)
__device__ float g_part[NROWS * 2];         // per-row exp-sum partial per col-half
__device__ float g_pos[NROWS];              // per-row positive logit

// ---------------------------------------------------------------------------
__device__ __forceinline__ uint32_t smem_u32(const void* p) {
    uint32_t a;
    asm("{ .reg .u64 t; cvta.to.shared.u64 t, %1; cvt.u32.u64 %0, t; }" : "=r"(a) : "l"(p));
    return a;
}
__device__ __forceinline__ void cp16(uint32_t dst, const void* src) {
    asm volatile("cp.async.cg.shared.global [%0], [%1], 16;" :: "r"(dst), "l"(src) : "memory");
}
#define CP_COMMIT() asm volatile("cp.async.commit_group;" ::: "memory")
#define CP_WAIT(n)  asm volatile("cp.async.wait_group %0;" :: "n"(n) : "memory")

__device__ __forceinline__ void ldsm4(uint32_t* r, uint32_t addr) {
    asm volatile("ldmatrix.sync.aligned.m8n8.x4.shared.b16 {%0,%1,%2,%3}, [%4];"
        : "=r"(r[0]), "=r"(r[1]), "=r"(r[2]), "=r"(r[3]) : "r"(addr));
}
__device__ __forceinline__ void mma16816(float* c, const uint32_t* a,
                                         uint32_t b0, uint32_t b1) {
    asm volatile("mma.sync.aligned.m16n8k16.row.col.f32.bf16.bf16.f32 "
        "{%0,%1,%2,%3}, {%4,%5,%6,%7}, {%8,%9}, {%0,%1,%2,%3};"
        : "+f"(c[0]), "+f"(c[1]), "+f"(c[2]), "+f"(c[3])
        : "r"(a[0]), "r"(a[1]), "r"(a[2]), "r"(a[3]), "r"(b0), "r"(b1));
}

// swizzled byte offset for (row, 16B-chunk) in a [rows x 512B] tile
__device__ __forceinline__ uint32_t swz_off(uint32_t row, uint32_t ch) {
    return row * 512u + ((ch ^ (row & 7u)) << 4);
}

// ---------------------------------------------------------------------------
// Kernel 1: L2-normalize rows -> bf16. One warp per row.
// ---------------------------------------------------------------------------
__global__ void __launch_bounds__(256) norm_kernel(const float* __restrict__ z1,
                                                   const float* __restrict__ z2) {
    int wid = threadIdx.x >> 5, lid = threadIdx.x & 31;
    int row = blockIdx.x * 8 + wid;
    const float* src = (row < HALF_N) ? z1 + (size_t)row * D
                                      : z2 + (size_t)(row - HALF_N) * D;
    const float4* s4 = (const float4*)src;
    float4 a = s4[lid], b = s4[lid + 32];
    float ss = a.x*a.x + a.y*a.y + a.z*a.z + a.w*a.w
             + b.x*b.x + b.y*b.y + b.z*b.z + b.w*b.w;
    #pragma unroll
    for (int o = 16; o > 0; o >>= 1) ss += __shfl_xor_sync(0xffffffffu, ss, o);
    float inv = 1.0f / fmaxf(sqrtf(ss), 1e-8f);
    __nv_bfloat162* d2 = (__nv_bfloat162*)(g_zn + (size_t)row * D);
    d2[2*lid]        = __floats2bfloat162_rn(a.x*inv, a.y*inv);
    d2[2*lid + 1]    = __floats2bfloat162_rn(a.z*inv, a.w*inv);
    d2[2*(lid+32)]   = __floats2bfloat162_rn(b.x*inv, b.y*inv);
    d2[2*(lid+32)+1] = __floats2bfloat162_rn(b.z*inv, b.w*inv);
}

// ---------------------------------------------------------------------------
// Kernel 2: mma.sync sim GEMM + fused exp/row-sum epilogue in registers.
// Grid 128 = 64 row-blocks x 2 col-halves. 8 warps; warp tile m32 x n64.
// ---------------------------------------------------------------------------
__global__ void __launch_bounds__(THREADS, 1) sim_kernel() {
    extern __shared__ char smem[];
    __shared__ float rowsum[MT];
    uint32_t sb = smem_u32(smem);

    int tid = threadIdx.x, wid = tid >> 5, lane = tid & 31;
    int rb = blockIdx.x >> 1, half = blockIdx.x & 1;
    int rgw = wid & 3;          // warp row-group: rows rgw*32 .. +31
    int cg  = wid >> 2;         // warp col-group: cols cg*64 .. +63

    if (tid < MT) rowsum[tid] = 0.0f;

    // ---- prologue: async-load A (group 0 includes B tile 0), then B tile 1
    const char* gA = (const char*)(g_zn + (size_t)rb * MT * D);
    const char* gB = (const char*)(g_zn + (size_t)half * HALF_N * D);
    #pragma unroll
    for (int i = 0; i < 16; i++) {
        uint32_t c = i * 256 + tid;             // chunk id in 128x32 chunks
        cp16(sb + SM_A + swz_off(c >> 5, c & 31), gA + (size_t)c * 16);
    }
    #pragma unroll
    for (int i = 0; i < 16; i++) {
        uint32_t c = i * 256 + tid;
        cp16(sb + SM_B0 + swz_off(c >> 5, c & 31), gB + (size_t)c * 16);
    }
    CP_COMMIT();                                // g0 = A + B0
    #pragma unroll
    for (int i = 0; i < 16; i++) {
        uint32_t c = i * 256 + tid;
        cp16(sb + SM_B0 + 65536 + swz_off(c >> 5, c & 31),
             gB + 65536 + (size_t)c * 16);
    }
    CP_COMMIT();                                // g1 = B1

    // ---- per-lane ldmatrix address components
    uint32_t lrow = (lane < 16) ? lane : lane - 16;   // row within 16-row block
    uint32_t lch  = lane >> 4;                        // +0 / +1 chunk
    // A: two 16-row blocks
    uint32_t aRow0 = rgw * 32 + lrow, aRow1 = aRow0 + 16;
    uint32_t aBase0 = sb + SM_A + aRow0 * 512, aSwz0 = aRow0 & 7;
    uint32_t aBase1 = sb + SM_A + aRow1 * 512, aSwz1 = aRow1 & 7;
    // B: four 16-row blocks (zn rows cg*64 + q*16)
    uint32_t bRow[4], bSwz[4];
    #pragma unroll
    for (int q = 0; q < 4; q++) { bRow[q] = (cg * 64 + q * 16 + lrow) * 512;
                                  bSwz[q] = (cg * 64 + q * 16 + lrow) & 7; }

    // ---- epilogue identity
    // thread covers rows: rb*128 + rgw*32 + rg*16 + lane/4 + 8*h   (rg,h in 0..1)
    int rlocBase = rgw * 32 + (lane >> 2);
    int giBase   = rb * MT + rlocBase;
    int colBase  = half * HALF_N + cg * 64 + ((lane & 3) << 1);
    int js       = rb & 31;                   // the one special tile
    bool diagCta = (half == (rb >> 5));       // else it's the positive tile

    float rsum[2][2] = {{0.f, 0.f}, {0.f, 0.f}};

    for (int j = 0; j < TIL; j++) {
        if (j == TIL - 1) { CP_WAIT(0); } else { CP_WAIT(1); }
        __syncthreads();
        uint32_t bBuf = sb + SM_B0 + (uint32_t)(j & 1) * 65536;

        float acc[2][8][4];
        #pragma unroll
        for (int rg = 0; rg < 2; rg++)
            #pragma unroll
            for (int nb = 0; nb < 8; nb++)
                #pragma unroll
                for (int e = 0; e < 4; e++) acc[rg][nb][e] = 0.f;

        #pragma unroll
        for (int k = 0; k < 16; k++) {
            uint32_t ch = 2 * k + lch;
            uint32_t a0[4], a1[4], b[4][4];
            ldsm4(a0, aBase0 + ((ch ^ aSwz0) << 4));
            ldsm4(a1, aBase1 + ((ch ^ aSwz1) << 4));
            #pragma unroll
            for (int q = 0; q < 4; q++)
                ldsm4(b[q], bBuf + bRow[q] + ((ch ^ bSwz[q]) << 4));
            #pragma unroll
            for (int q = 0; q < 4; q++) {
                mma16816(acc[0][2*q],   a0, b[q][0], b[q][2]);
                mma16816(acc[0][2*q+1], a0, b[q][1], b[q][3]);
                mma16816(acc[1][2*q],   a1, b[q][0], b[q][2]);
                mma16816(acc[1][2*q+1], a1, b[q][1], b[q][3]);
            }
        }

        __syncthreads();                       // all warps done reading bBuf
        if (j + 2 < TIL) {                     // prefetch tile j+2 into bBuf
            const char* src = gB + (size_t)(j + 2) * 65536;
            #pragma unroll
            for (int i = 0; i < 16; i++) {
                uint32_t c = i * 256 + tid;
                cp16(bBuf + swz_off(c >> 5, c & 31), src + (size_t)c * 16);
            }
            CP_COMMIT();
        }

        // ---- fused epilogue on register fragments
        if (j != js) {
            #pragma unroll
            for (int rg = 0; rg < 2; rg++)
                #pragma unroll
                for (int nb = 0; nb < 8; nb++)
                    #pragma unroll
                    for (int e2 = 0; e2 < 4; e2++)
                        rsum[rg][e2 >> 1] += __expf(2.f * acc[rg][nb][e2]);
        } else {
            #pragma unroll
            for (int rg = 0; rg < 2; rg++) {
                #pragma unroll
                for (int e2 = 0; e2 < 4; e2++) {
                    int h = e2 >> 1;
                    int gi = giBase + rg * 16 + 8 * h;
                    int gtgt = diagCta ? gi
                                       : ((gi < HALF_N) ? gi + HALF_N : gi - HALF_N);
                    #pragma unroll
                    for (int nb = 0; nb < 8; nb++) {
                        float sim = 2.f * acc[rg][nb][e2];
                        int gj = colBase + j * NT + nb * 8 + (e2 & 1);
                        if (diagCta) {
                            if (gj != gtgt) rsum[rg][h] += __expf(sim);
                        } else {
                            rsum[rg][h] += __expf(sim);
                            if (gj == gtgt) g_pos[gi] = sim;
                        }
                    }
                }
            }
        }
    }

    // ---- reduce 4 lanes sharing the same rows, combine col-groups via smem
    #pragma unroll
    for (int rg = 0; rg < 2; rg++)
        #pragma unroll
        for (int h = 0; h < 2; h++) {
            float v = rsum[rg][h];
            v += __shfl_xor_sync(0xffffffffu, v, 1);
            v += __shfl_xor_sync(0xffffffffu, v, 2);
            if ((lane & 3) == 0)
                atomicAdd(&rowsum[rlocBase + rg * 16 + 8 * h], v);
        }
    __syncthreads();
    if (tid < MT)
        g_part[(size_t)(rb * MT + tid) * 2 + half] = rowsum[tid];
}

// ---------------------------------------------------------------------------
// Kernel 3: combine partials -> mean loss.
// ---------------------------------------------------------------------------
__global__ void reduce_kernel(float* __restrict__ out) {
    __shared__ float red[256];
    int t = threadIdx.x;
    float s = 0.0f;
    for (int i = t; i < NROWS; i += 256)
        s += logf(g_part[2*i] + g_part[2*i + 1]) - g_pos[i];
    red[t] = s;
    __syncthreads();
    #pragma unroll
    for (int k = 128; k > 0; k >>= 1) {
        if (t < k) red[t] += red[t + k];
        __syncthreads();
    }
    if (t == 0) out[0] = red[0] / (float)NROWS;
}

// ---------------------------------------------------------------------------
extern "C" void kernel_launch(void* const* d_in, const int* in_sizes, int n_in,
                              void* d_out, int out_size) {
    const float* z1 = (const float*)d_in[0];
    const float* z2 = (const float*)d_in[1];
    float* out = (float*)d_out;

    cudaFuncSetAttribute(sim_kernel,
                         cudaFuncAttributeMaxDynamicSharedMemorySize, SMEM_TOTAL);

    norm_kernel<<<NROWS / 8, 256>>>(z1, z2);
    sim_kernel<<<128, THREADS, SMEM_TOTAL>>>();
    reduce_kernel<<<1, 256>>>(out);
}